// round 2
// baseline (speedup 1.0000x reference)
#include <cuda_runtime.h>
#include <math.h>

#define N_MAX 100000
#define E_MAX 1600000
#define SCAN_B 1024

// ---------------- scratch (device globals; allocation-free) ----------------
__device__ float g_dinv[N_MAX];                      // rsqrt(deg)
__device__ int   g_cnt [N_MAX];                      // in-degree count, then fill cursor
__device__ int   g_off [N_MAX + 1];                  // CSR offsets (exclusive scan)
__device__ int   g_bsum[SCAN_B];                     // scan block sums
__device__ int   g_csr [E_MAX];                      // CSR: src indices grouped by dst
__device__ __align__(16) float g_h1[N_MAX * 32];     // x @ W1
__device__ __align__(16) float g_h2[N_MAX * 16];     // layer-1 output @ W2

// ---------------- CSR build ----------------

__global__ void k_zero(int n) {
    int i = blockIdx.x * blockDim.x + threadIdx.x;
    if (i < n) g_cnt[i] = 0;
}

__global__ void k_count(const int* __restrict__ dst, int e) {
    int i = blockIdx.x * blockDim.x + threadIdx.x;
    if (i < e) atomicAdd(&g_cnt[__ldg(dst + i)], 1);
}

// block-local exclusive scan (1024 elems/block), write block totals
__global__ void k_scan_a(int n) {
    __shared__ int sh[SCAN_B];
    int tid = threadIdx.x;
    int i = blockIdx.x * SCAN_B + tid;
    int v = (i < n) ? g_cnt[i] : 0;
    sh[tid] = v;
    __syncthreads();
#pragma unroll
    for (int ofs = 1; ofs < SCAN_B; ofs <<= 1) {
        int t = (tid >= ofs) ? sh[tid - ofs] : 0;
        __syncthreads();
        sh[tid] += t;
        __syncthreads();
    }
    int incl = sh[tid];
    if (i < n) g_off[i] = incl - v;           // local exclusive
    if (tid == SCAN_B - 1) g_bsum[blockIdx.x] = incl;
}

// scan the block sums (single block)
__global__ void k_scan_b(int nb) {
    __shared__ int sh[SCAN_B];
    int tid = threadIdx.x;
    int v = (tid < nb) ? g_bsum[tid] : 0;
    sh[tid] = v;
    __syncthreads();
#pragma unroll
    for (int ofs = 1; ofs < SCAN_B; ofs <<= 1) {
        int t = (tid >= ofs) ? sh[tid - ofs] : 0;
        __syncthreads();
        sh[tid] += t;
        __syncthreads();
    }
    if (tid < nb) g_bsum[tid] = sh[tid] - v;  // exclusive
}

// globalize offsets; compute dinv = rsqrt(deg+1); set off[n]
__global__ void k_scan_c(int n) {
    int i = blockIdx.x * blockDim.x + threadIdx.x;
    if (i >= n) return;
    int c = g_cnt[i];
    int o = g_off[i] + g_bsum[i >> 10];
    g_off[i] = o;
    g_dinv[i] = rsqrtf((float)c + 1.0f);
    if (i == n - 1) g_off[n] = o + c;
}

// scatter edges into CSR slots; consumes g_cnt as a descending cursor
__global__ void k_fill(const int* __restrict__ src, const int* __restrict__ dst, int e) {
    int i = blockIdx.x * blockDim.x + threadIdx.x;
    if (i >= e) return;
    int d = __ldg(dst + i);
    int r = atomicSub(&g_cnt[d], 1);          // returns old value: count..1
    g_csr[g_off[d] + r - 1] = __ldg(src + i);
}

// ---------------- dense layers + gathers ----------------

// h1 = x @ W1 (256 thr = 32 nodes x 8 groups of 4 channels)
__global__ void k_mm1(const float* __restrict__ x, const float* __restrict__ W1, int n) {
    __shared__ float sW[8 * 32];
    int tid = threadIdx.x;
    if (tid < 256) sW[tid] = __ldg(W1 + tid);
    __syncthreads();
    int node = blockIdx.x * 32 + (tid >> 3);
    int g = tid & 7;
    if (node >= n) return;

    const float4* xr = reinterpret_cast<const float4*>(x + node * 8);
    float4 x0 = __ldg(xr), x1 = __ldg(xr + 1);
    float xv[8] = {x0.x, x0.y, x0.z, x0.w, x1.x, x1.y, x1.z, x1.w};

    float o[4];
#pragma unroll
    for (int j = 0; j < 4; j++) {
        int c = g * 4 + j;
        float s = 0.f;
#pragma unroll
        for (int k = 0; k < 8; k++) s = fmaf(xv[k], sW[k * 32 + c], s);
        o[j] = s;
    }
    *reinterpret_cast<float4*>(g_h1 + node * 32 + g * 4) = make_float4(o[0], o[1], o[2], o[3]);
}

// layer-1 aggregate + bias + relu + @W2, warp per node (lane = feature)
__global__ void k_agg1(const float* __restrict__ b1, const float* __restrict__ W2, int n) {
    __shared__ float sW[32 * 16];
    __shared__ float sb[32];
    __shared__ float sv[8][33];               // per-warp feature exchange (+pad)
    int tid = threadIdx.x;
    sW[tid] = __ldg(W2 + tid);
    sW[tid + 256] = __ldg(W2 + tid + 256);
    if (tid < 32) sb[tid] = __ldg(b1 + tid);
    __syncthreads();

    int wl = tid >> 5;
    int lane = tid & 31;
    int w = blockIdx.x * 8 + wl;
    if (w >= n) return;

    float di = __ldg(&g_dinv[w]);
    float acc = g_h1[w * 32 + lane] * di * di;   // self-loop
    int j0 = g_off[w], j1 = g_off[w + 1];
#pragma unroll 2
    for (int j = j0; j < j1; ++j) {
        int s = __ldg(&g_csr[j]);                 // warp-broadcast
        float nm = __ldg(&g_dinv[s]) * di;        // warp-broadcast
        acc = fmaf(g_h1[s * 32 + lane], nm, acc); // coalesced 128B line
    }
    sv[wl][lane] = fmaxf(acc + sb[lane], 0.f);
    __syncwarp();
    if (lane < 16) {
        float s = 0.f;
#pragma unroll
        for (int k = 0; k < 32; k++) s = fmaf(sv[wl][k], sW[k * 16 + lane], s);
        g_h2[w * 16 + lane] = s;
    }
}

// layer-2 aggregate + bias + relu + FC + sigmoid, half-warp per node
__global__ void k_agg2(const float* __restrict__ b2, const float* __restrict__ Wfc,
                       const float* __restrict__ bfc, float* __restrict__ out, int n) {
    __shared__ float swf[16];
    __shared__ float sb[16];
    int tid = threadIdx.x;
    if (tid < 16) { swf[tid] = __ldg(Wfc + tid); sb[tid] = __ldg(b2 + tid); }
    __syncthreads();

    int node = blockIdx.x * 16 + (tid >> 4);
    int lane = tid & 15;
    bool valid = node < n;

    float v = 0.f;
    if (valid) {
        float di = __ldg(&g_dinv[node]);
        float acc = g_h2[node * 16 + lane] * di * di;
        int j0 = g_off[node], j1 = g_off[node + 1];
#pragma unroll 2
        for (int j = j0; j < j1; ++j) {
            int s = __ldg(&g_csr[j]);
            float nm = __ldg(&g_dinv[s]) * di;
            acc = fmaf(g_h2[s * 16 + lane], nm, acc);
        }
        v = fmaxf(acc + sb[lane], 0.f) * swf[lane];
    }
#pragma unroll
    for (int o = 8; o > 0; o >>= 1) v += __shfl_down_sync(0xffffffffu, v, o, 16);
    if (valid && lane == 0) out[node] = 1.0f / (1.0f + expf(-(v + __ldg(bfc))));
}

// ---------------- launch ----------------
extern "C" void kernel_launch(void* const* d_in, const int* in_sizes, int n_in,
                              void* d_out, int out_size) {
    const float* x   = (const float*)d_in[0];
    const int*   ei  = (const int*)d_in[1];
    const float* W1  = (const float*)d_in[2];
    const float* b1  = (const float*)d_in[3];
    const float* W2  = (const float*)d_in[4];
    const float* b2  = (const float*)d_in[5];
    const float* Wfc = (const float*)d_in[6];
    const float* bfc = (const float*)d_in[7];
    float* out = (float*)d_out;

    int n = in_sizes[0] / 8;        // 100000
    int e = in_sizes[1] / 2;        // 1600000
    const int* src = ei;
    const int* dst = ei + e;

    const int B = 256;
    int gn = (n + B - 1) / B;
    int ge = (e + B - 1) / B;
    int nb = (n + SCAN_B - 1) / SCAN_B;

    k_zero  <<<gn, B>>>(n);
    k_count <<<ge, B>>>(dst, e);
    k_scan_a<<<nb, SCAN_B>>>(n);
    k_scan_b<<<1,  SCAN_B>>>(nb);
    k_scan_c<<<gn, B>>>(n);
    k_fill  <<<ge, B>>>(src, dst, e);

    k_mm1 <<<(n + 31) / 32, B>>>(x, W1, n);
    k_agg1<<<(n + 7)  / 8,  B>>>(b1, W2, n);
    k_agg2<<<(n + 15) / 16, B>>>(b2, Wfc, bfc, out, n);
}

// round 4
// speedup vs baseline: 1.0826x; 1.0826x over previous
#include <cuda_runtime.h>
#include <math.h>

#define N_MAX 100000
#define E_MAX 1600000

// ---------------- scratch (device globals; allocation-free) ----------------
__device__ int   g_cnt [N_MAX];                      // in-degree; consumed as fill cursor
__device__ int   g_deg [N_MAX];                      // in-degree (persistent)
__device__ int   g_off [N_MAX];                      // CSR segment start (unordered)
__device__ int   g_cursor;                           // global bump allocator
__device__ float g_dinv[N_MAX];                      // rsqrt(deg+1)
__device__ int   g_csr [E_MAX];                      // src indices grouped by dst
__device__ __align__(16) float g_h1[N_MAX * 32];     // x @ W1
__device__ __align__(16) float g_h2[N_MAX * 16];     // layer-1 out @ W2

// ---------------- CSR build (no scan) ----------------

__global__ void k_init(int n) {
    int i = blockIdx.x * blockDim.x + threadIdx.x;
    if (i < n) g_cnt[i] = 0;
    if (i == 0) g_cursor = 0;
}

__global__ void k_count(const int* __restrict__ dst, int e) {
    int i = blockIdx.x * blockDim.x + threadIdx.x;
    if (i < e) atomicAdd(&g_cnt[__ldg(dst + i)], 1);
}

// segment placement via bump allocator; dinv too
__global__ void k_off(int n) {
    int i = blockIdx.x * blockDim.x + threadIdx.x;
    if (i >= n) return;
    int c = g_cnt[i];
    g_deg[i] = c;
    g_off[i] = atomicAdd(&g_cursor, c);
    g_dinv[i] = rsqrtf((float)c + 1.0f);
}

__global__ void k_fill(const int* __restrict__ src, const int* __restrict__ dst, int e) {
    int i = blockIdx.x * blockDim.x + threadIdx.x;
    if (i >= e) return;
    int d = __ldg(dst + i);
    int r = atomicSub(&g_cnt[d], 1);          // old value: count..1
    g_csr[g_off[d] + r - 1] = __ldg(src + i);
}

// ---------------- dense layers + gathers ----------------

// h1 = x @ W1 (256 thr = 32 nodes x 8 groups of 4 channels)
__global__ void k_mm1(const float* __restrict__ x, const float* __restrict__ W1, int n) {
    __shared__ float sW[8 * 32];
    int tid = threadIdx.x;
    if (tid < 256) sW[tid] = __ldg(W1 + tid);
    __syncthreads();
    int node = blockIdx.x * 32 + (tid >> 3);
    int g = tid & 7;
    if (node >= n) return;

    const float4* xr = reinterpret_cast<const float4*>(x + node * 8);
    float4 x0 = __ldg(xr), x1 = __ldg(xr + 1);
    float xv[8] = {x0.x, x0.y, x0.z, x0.w, x1.x, x1.y, x1.z, x1.w};

    float o[4];
#pragma unroll
    for (int j = 0; j < 4; j++) {
        int c = g * 4 + j;
        float s = 0.f;
#pragma unroll
        for (int k = 0; k < 8; k++) s = fmaf(xv[k], sW[k * 32 + c], s);
        o[j] = s;
    }
    *reinterpret_cast<float4*>(g_h1 + node * 32 + g * 4) = make_float4(o[0], o[1], o[2], o[3]);
}

// layer-1 aggregate + bias + relu + @W2 ; warp per node, lane = feature, MLP=4
__global__ void k_agg1(const float* __restrict__ b1, const float* __restrict__ W2, int n) {
    __shared__ float sW[32 * 16];
    __shared__ float sb[32];
    __shared__ float sv[8][33];
    int tid = threadIdx.x;
    sW[tid] = __ldg(W2 + tid);
    sW[tid + 256] = __ldg(W2 + tid + 256);
    if (tid < 32) sb[tid] = __ldg(b1 + tid);
    __syncthreads();

    int wl = tid >> 5;
    int lane = tid & 31;
    int w = blockIdx.x * 8 + wl;
    if (w >= n) return;

    float di = __ldg(&g_dinv[w]);
    float acc = g_h1[w * 32 + lane] * di * di;      // self-loop
    int j0 = __ldg(&g_off[w]);
    int deg = __ldg(&g_deg[w]);
    int j1 = j0 + deg;
    int j = j0;

    // 4 independent neighbor chains per iteration
    for (; j + 4 <= j1; j += 4) {
        int s0 = __ldg(&g_csr[j + 0]);
        int s1 = __ldg(&g_csr[j + 1]);
        int s2 = __ldg(&g_csr[j + 2]);
        int s3 = __ldg(&g_csr[j + 3]);
        float n0 = __ldg(&g_dinv[s0]);
        float n1 = __ldg(&g_dinv[s1]);
        float n2 = __ldg(&g_dinv[s2]);
        float n3 = __ldg(&g_dinv[s3]);
        float h0 = g_h1[s0 * 32 + lane];
        float h1v = g_h1[s1 * 32 + lane];
        float h2v = g_h1[s2 * 32 + lane];
        float h3 = g_h1[s3 * 32 + lane];
        acc = fmaf(h0, n0 * di, acc);
        acc = fmaf(h1v, n1 * di, acc);
        acc = fmaf(h2v, n2 * di, acc);
        acc = fmaf(h3, n3 * di, acc);
    }
    for (; j < j1; ++j) {
        int s = __ldg(&g_csr[j]);
        acc = fmaf(g_h1[s * 32 + lane], __ldg(&g_dinv[s]) * di, acc);
    }

    sv[wl][lane] = fmaxf(acc + sb[lane], 0.f);
    __syncwarp();
    if (lane < 16) {
        float s = 0.f;
#pragma unroll
        for (int k = 0; k < 32; k++) s = fmaf(sv[wl][k], sW[k * 16 + lane], s);
        g_h2[w * 16 + lane] = s;
    }
}

// layer-2 aggregate + bias + relu + FC + sigmoid ; 16 lanes per node, MLP=4
__global__ void k_agg2(const float* __restrict__ b2, const float* __restrict__ Wfc,
                       const float* __restrict__ bfc, float* __restrict__ out, int n) {
    __shared__ float swf[16];
    __shared__ float sb[16];
    int tid = threadIdx.x;
    if (tid < 16) { swf[tid] = __ldg(Wfc + tid); sb[tid] = __ldg(b2 + tid); }
    __syncthreads();

    int node = blockIdx.x * 16 + (tid >> 4);
    int lane = tid & 15;
    bool valid = node < n;

    float v = 0.f;
    if (valid) {
        float di = __ldg(&g_dinv[node]);
        float acc = g_h2[node * 16 + lane] * di * di;
        int j0 = __ldg(&g_off[node]);
        int deg = __ldg(&g_deg[node]);
        int j1 = j0 + deg;
        int j = j0;
        for (; j + 4 <= j1; j += 4) {
            int s0 = __ldg(&g_csr[j + 0]);
            int s1 = __ldg(&g_csr[j + 1]);
            int s2 = __ldg(&g_csr[j + 2]);
            int s3 = __ldg(&g_csr[j + 3]);
            float n0 = __ldg(&g_dinv[s0]);
            float n1 = __ldg(&g_dinv[s1]);
            float n2 = __ldg(&g_dinv[s2]);
            float n3 = __ldg(&g_dinv[s3]);
            float h0 = g_h2[s0 * 16 + lane];
            float h1v = g_h2[s1 * 16 + lane];
            float h2v = g_h2[s2 * 16 + lane];
            float h3 = g_h2[s3 * 16 + lane];
            acc = fmaf(h0, n0 * di, acc);
            acc = fmaf(h1v, n1 * di, acc);
            acc = fmaf(h2v, n2 * di, acc);
            acc = fmaf(h3, n3 * di, acc);
        }
        for (; j < j1; ++j) {
            int s = __ldg(&g_csr[j]);
            acc = fmaf(g_h2[s * 16 + lane], __ldg(&g_dinv[s]) * di, acc);
        }
        v = fmaxf(acc + sb[lane], 0.f) * swf[lane];
    }
#pragma unroll
    for (int o = 8; o > 0; o >>= 1) v += __shfl_down_sync(0xffffffffu, v, o, 16);
    if (valid && lane == 0) out[node] = 1.0f / (1.0f + expf(-(v + __ldg(bfc))));
}

// ---------------- launch ----------------
extern "C" void kernel_launch(void* const* d_in, const int* in_sizes, int n_in,
                              void* d_out, int out_size) {
    const float* x   = (const float*)d_in[0];
    const int*   ei  = (const int*)d_in[1];
    const float* W1  = (const float*)d_in[2];
    const float* b1  = (const float*)d_in[3];
    const float* W2  = (const float*)d_in[4];
    const float* b2  = (const float*)d_in[5];
    const float* Wfc = (const float*)d_in[6];
    const float* bfc = (const float*)d_in[7];
    float* out = (float*)d_out;

    int n = in_sizes[0] / 8;        // 100000
    int e = in_sizes[1] / 2;        // 1600000
    const int* src = ei;
    const int* dst = ei + e;

    const int B = 256;
    int gn = (n + B - 1) / B;
    int ge = (e + B - 1) / B;

    k_init <<<gn, B>>>(n);
    k_count<<<ge, B>>>(dst, e);
    k_off  <<<gn, B>>>(n);
    k_fill <<<ge, B>>>(src, dst, e);

    k_mm1 <<<(n + 31) / 32, B>>>(x, W1, n);
    k_agg1<<<(n + 7)  / 8,  B>>>(b1, W2, n);
    k_agg2<<<(n + 15) / 16, B>>>(b2, Wfc, bfc, out, n);
}

// round 10
// speedup vs baseline: 1.7886x; 1.6520x over previous
#include <cuda_runtime.h>
#include <math.h>

#define N_MAX 100000
#define E_MAX 1600000

// ---------------- scratch (device globals; allocation-free) ----------------
__device__ float g_deg [N_MAX];                       // degree (incl self-loop), float
__device__ float g_dinv[N_MAX];                       // rsqrt(deg)
__device__ __align__(16) float g_y1  [N_MAX * 8];     // x * dinv       (pre-scaled src msg)
__device__ __align__(16) float g_accx[N_MAX * 8];     // Σ y1 over in-nbrs + self
__device__ __align__(16) float g_y2  [N_MAX * 16];    // h2 * dinv
__device__ __align__(16) float g_acc2[N_MAX * 16];    // Σ y2 over in-nbrs + self

// ---------------- degree ----------------
__global__ void k_zero(int n) {
    int i = blockIdx.x * blockDim.x + threadIdx.x;
    if (i < n) g_deg[i] = 1.0f;                       // self-loop
}

__global__ void k_count(const int* __restrict__ dst, int e) {
    int i = blockIdx.x * blockDim.x + threadIdx.x;
    if (i < e) atomicAdd(&g_deg[__ldg(dst + i)], 1.0f);   // RED (no return use)
}

// dinv, y1 = x*dinv, acc_x init = y1 (self term; post-scaled later).
// 2 lanes per node, float4 each.
__global__ void k_prep(const float* __restrict__ x, int n) {
    int t = blockIdx.x * blockDim.x + threadIdx.x;
    int node = t >> 1;
    if (node >= n) return;
    int g = t & 1;
    float di = rsqrtf(g_deg[node]);
    if (g == 0) g_dinv[node] = di;
    float4 xv = __ldg(reinterpret_cast<const float4*>(x + node * 8) + g);
    float4 yv = make_float4(xv.x * di, xv.y * di, xv.z * di, xv.w * di);
    *(reinterpret_cast<float4*>(g_y1 + node * 8) + g) = yv;
    *(reinterpret_cast<float4*>(g_accx + node * 8) + g) = yv;
}

// layer-1 scatter on RAW INPUT features (8-dim): acc_x[d] += y1[s]
__global__ void k_edge1(const int* __restrict__ src, const int* __restrict__ dst, int e) {
    int t = blockIdx.x * blockDim.x + threadIdx.x;
    int ed = t >> 1;
    if (ed >= e) return;
    int g = t & 1;
    int s = __ldg(src + ed);
    int d = __ldg(dst + ed);
    float4 v = __ldg(reinterpret_cast<const float4*>(g_y1 + s * 8) + g);
    atomicAdd(reinterpret_cast<float4*>(g_accx + d * 8) + g, v);
}

// per node: a = acc_x*dinv (true layer-1 aggregate),
// v = relu(a@W1+b1), h2 = v@W2, emit y2 = h2*dinv into both y2 and acc2.
__global__ void k_mid(const float* __restrict__ W1, const float* __restrict__ b1,
                      const float* __restrict__ W2, int n) {
    __shared__ float sW1[8 * 32];
    __shared__ float sW2[32 * 16];
    __shared__ float sb1[32];
    int tid = threadIdx.x;
    if (tid < 256) sW1[tid] = __ldg(W1 + tid);
    sW2[tid] = __ldg(W2 + tid);
    sW2[tid + 256] = __ldg(W2 + tid + 256);
    if (tid < 32) sb1[tid] = __ldg(b1 + tid);
    __syncthreads();

    int node = blockIdx.x * blockDim.x + tid;
    if (node >= n) return;
    float di = g_dinv[node];

    float a[8];
    float4 a0 = *reinterpret_cast<const float4*>(g_accx + node * 8);
    float4 a1 = *(reinterpret_cast<const float4*>(g_accx + node * 8) + 1);
    a[0] = a0.x * di; a[1] = a0.y * di; a[2] = a0.z * di; a[3] = a0.w * di;
    a[4] = a1.x * di; a[5] = a1.y * di; a[6] = a1.z * di; a[7] = a1.w * di;

    float v[32];
#pragma unroll
    for (int c = 0; c < 32; c++) {
        float s = sb1[c];
#pragma unroll
        for (int k = 0; k < 8; k++) s = fmaf(a[k], sW1[k * 32 + c], s);
        v[c] = fmaxf(s, 0.f);
    }
#pragma unroll
    for (int q = 0; q < 4; q++) {
        float o[4];
#pragma unroll
        for (int j = 0; j < 4; j++) {
            int c = q * 4 + j;
            float s = 0.f;
#pragma unroll
            for (int k = 0; k < 32; k++) s = fmaf(v[k], sW2[k * 16 + c], s);
            o[j] = s * di;                         // pre-scale by dinv
        }
        float4 yv = make_float4(o[0], o[1], o[2], o[3]);
        *(reinterpret_cast<float4*>(g_y2 + node * 16) + q) = yv;
        *(reinterpret_cast<float4*>(g_acc2 + node * 16) + q) = yv;
    }
}

// layer-2 scatter (16-dim): acc2[d] += y2[s]
__global__ void k_edge2(const int* __restrict__ src, const int* __restrict__ dst, int e) {
    int t = blockIdx.x * blockDim.x + threadIdx.x;
    int ed = t >> 2;
    if (ed >= e) return;
    int g = t & 3;
    int s = __ldg(src + ed);
    int d = __ldg(dst + ed);
    float4 v = __ldg(reinterpret_cast<const float4*>(g_y2 + s * 16) + g);
    atomicAdd(reinterpret_cast<float4*>(g_acc2 + d * 16) + g, v);
}

// out = sigmoid(relu(acc2*dinv + b2) @ Wfc + bfc)
__global__ void k_fin(const float* __restrict__ b2, const float* __restrict__ Wfc,
                      const float* __restrict__ bfc, float* __restrict__ out, int n) {
    __shared__ float swf[16];
    __shared__ float sb[16];
    __shared__ float sbf;
    int tid = threadIdx.x;
    if (tid < 16) { swf[tid] = __ldg(Wfc + tid); sb[tid] = __ldg(b2 + tid); }
    if (tid == 0) sbf = __ldg(bfc);
    __syncthreads();

    int i = blockIdx.x * blockDim.x + tid;
    if (i >= n) return;
    float di = g_dinv[i];
    float s = sbf;
#pragma unroll
    for (int q = 0; q < 4; q++) {
        float4 a = *(reinterpret_cast<const float4*>(g_acc2 + i * 16) + q);
        s = fmaf(fmaxf(a.x * di + sb[q * 4 + 0], 0.f), swf[q * 4 + 0], s);
        s = fmaf(fmaxf(a.y * di + sb[q * 4 + 1], 0.f), swf[q * 4 + 1], s);
        s = fmaf(fmaxf(a.z * di + sb[q * 4 + 2], 0.f), swf[q * 4 + 2], s);
        s = fmaf(fmaxf(a.w * di + sb[q * 4 + 3], 0.f), swf[q * 4 + 3], s);
    }
    out[i] = 1.0f / (1.0f + expf(-s));
}

// ---------------- launch ----------------
extern "C" void kernel_launch(void* const* d_in, const int* in_sizes, int n_in,
                              void* d_out, int out_size) {
    const float* x   = (const float*)d_in[0];
    const int*   ei  = (const int*)d_in[1];
    const float* W1  = (const float*)d_in[2];
    const float* b1  = (const float*)d_in[3];
    const float* W2  = (const float*)d_in[4];
    const float* b2  = (const float*)d_in[5];
    const float* Wfc = (const float*)d_in[6];
    const float* bfc = (const float*)d_in[7];
    float* out = (float*)d_out;

    int n = in_sizes[0] / 8;        // 100000
    int e = in_sizes[1] / 2;        // 1600000
    const int* src = ei;
    const int* dst = ei + e;

    const int B = 256;
    int gn = (n + B - 1) / B;

    k_zero <<<gn, B>>>(n);
    k_count<<<(e + 511) / 512, 512>>>(dst, e);
    k_prep <<<(n * 2 + B - 1) / B, B>>>(x, n);
    k_edge1<<<(int)(((long long)e * 2 + B - 1) / B), B>>>(src, dst, e);
    k_mid  <<<gn, B>>>(W1, b1, W2, n);
    k_edge2<<<(int)(((long long)e * 4 + B - 1) / B), B>>>(src, dst, e);
    k_fin  <<<gn, B>>>(b2, Wfc, bfc, out, n);
}